// round 4
// baseline (speedup 1.0000x reference)
#include <cuda_runtime.h>
#include <cuda_bf16.h>
#include <math.h>
#include <stdint.h>

#define BB 512
#define TT 16
#define DD 256
#define LL 16
#define NTGT 32
#define NROW (BB*TT)

// ---------------- scratch (device globals) ----------------------------------
__device__ float         g_emb  [NROW*DD];             // fp32 emb    8 MB
__device__ unsigned char g_emb8 [NROW*DD];             // e4m3 emb*64 2 MB
__device__ unsigned char g_w8   [LL*LL*DD*DD];         // e4m3 w*64  16.7 MB
__device__ float         g_opart[LL*BB*DD];            // per-l o     8 MB
__device__ float         g_o    [BB*DD];
__device__ float         g_z    [BB*DD];

// ---------------- helpers ----------------------------------------------------
__device__ __forceinline__ uint32_t smem_u32(const void* p) {
    uint32_t a;
    asm("{ .reg .u64 t; cvta.to.shared.u64 t, %1; cvt.u32.u64 %0, t; }"
        : "=r"(a) : "l"(p));
    return a;
}
__device__ __forceinline__ void cpa16(uint32_t s, const void* g) {
    asm volatile("cp.async.cg.shared.global [%0], [%1], 16;"
                 :: "r"(s), "l"(g) : "memory");
}
#define CP_COMMIT() asm volatile("cp.async.commit_group;" ::: "memory")

__device__ __forceinline__ void ldsm4(uint32_t (&r)[4], uint32_t a) {
    asm volatile("ldmatrix.sync.aligned.m8n8.x4.shared.b16 {%0,%1,%2,%3}, [%4];"
                 : "=r"(r[0]), "=r"(r[1]), "=r"(r[2]), "=r"(r[3]) : "r"(a));
}
// fp8 e4m3 MMA, K=32 per instruction
__device__ __forceinline__ void mma_fp8(float (&c)[4], const uint32_t (&a)[4],
                                        uint32_t b0, uint32_t b1) {
    asm volatile(
        "mma.sync.aligned.m16n8k32.row.col.f32.e4m3.e4m3.f32 "
        "{%0,%1,%2,%3}, {%4,%5,%6,%7}, {%8,%9}, {%0,%1,%2,%3};"
        : "+f"(c[0]), "+f"(c[1]), "+f"(c[2]), "+f"(c[3])
        : "r"(a[0]), "r"(a[1]), "r"(a[2]), "r"(a[3]), "r"(b0), "r"(b1));
}
__device__ __forceinline__ uint16_t cvt_e4m3x2(float hi, float lo) {
    uint16_t r;
    asm("cvt.rn.satfinite.e4m3x2.f32 %0, %1, %2;" : "=h"(r) : "f"(hi), "f"(lo));
    return r;   // low byte = lo, high byte = hi
}

// sigmoid for x>=0, tiny-|x| fast path (conv_out magnitudes are ~<0.1)
__device__ __forceinline__ float sigmoid_pos(float x) {
    if (x < 0.25f) {
        float x2 = x * x;
        float p = fmaf(x2, 1.0f / 480.0f, -1.0f / 48.0f);
        p = fmaf(x2, p, 0.25f);
        return fmaf(x, p, 0.5f);
    }
    return 1.0f / (1.0f + expf(-x));
}

// ---------------- 0a) gather item embeddings (fp32 + e4m3*64) ---------------
__global__ void gather_emb_kernel(const int* __restrict__ seq,
                                  const float* __restrict__ item_emb) {
    int row = blockIdx.x;
    int idx = seq[row];
    float4 v = ((const float4*)(item_emb + (size_t)idx * DD))[threadIdx.x];
    ((float4*)(g_emb + (size_t)row * DD))[threadIdx.x] = v;
    uint32_t p01 = cvt_e4m3x2(v.y * 64.f, v.x * 64.f);
    uint32_t p23 = cvt_e4m3x2(v.w * 64.f, v.z * 64.f);
    ((uint32_t*)g_emb8)[(size_t)row * 64 + threadIdx.x] = p01 | (p23 << 16);
}

// ---------------- 0b) conv_w fp32 -> e4m3*64 (valid pairs only) --------------
__global__ void wconv_kernel(const float* __restrict__ conv_w,
                             const int* __restrict__ pair_lut) {
    int p = blockIdx.y;
    int lm = pair_lut[p];                 // l*16+m, m<=l
    size_t base = (size_t)lm * DD * DD;
    int i = blockIdx.x * 256 + threadIdx.x;     // float4 index, 16384 per pair
    float4 v = ((const float4*)(conv_w + base))[i];
    uint32_t p01 = cvt_e4m3x2(v.y * 64.f, v.x * 64.f);
    uint32_t p23 = cvt_e4m3x2(v.w * 64.f, v.z * 64.f);
    ((uint32_t*)(g_w8 + base))[i] = p01 | (p23 << 16);
}
__device__ int d_pair_lut[136];
__global__ void build_lut_kernel() {
    int p = threadIdx.x;
    if (p < 136) {
        int l = 0, a = 0;
        while (a + l + 1 <= p) { a += l + 1; l++; }
        d_pair_lut[p] = l * 16 + (p - a);
    }
}

// ---------------- 1) fused windowed fp8 GEMM + gate + QRNN -------------------
// CTA: l fixed, 8 b x 16 t (128 M-rows) x 128 c. K = (m<=l) x 256 d (fp8).
// smem: A [128 rows][272B] (256B payload), zero row 272B,
//       B buf x3 [128 c][144B] (128B payload). Epilogue reuses A region (fp32).
#define AST_B   272
#define BST_B   144
#define A_SZ    (128*AST_B)            // 34816
#define ZOFF    A_SZ
#define B_OFF0  (A_SZ + AST_B)         // 35088 (16B aligned)
#define B_SZ    (128*BST_B)            // 18432
#define SMEM_REQ (B_OFF0 + 3*B_SZ)     // 90384
#define EST_F   132                    // epilogue fp32 row stride (floats)

__global__ void __launch_bounds__(256, 2)
conv_fused_kernel(const float* __restrict__ conv_b) {
    extern __shared__ char smp[];
    const uint32_t sb = smem_u32(smp);
    const int tid = threadIdx.x, wid = tid >> 5, lane = tid & 31;
    const int warpM = wid >> 2, warpN = wid & 3;    // warpM 0..1, warpN 0..3

    const int l  = 15 - blockIdx.z;
    const int b0 = blockIdx.y * 8;
    const int c0 = blockIdx.x * 128;

    // ---- stage A panel: 128 rows x 256B fp8 ----
    {
        const uint4* src = (const uint4*)g_emb8 + (size_t)b0 * TT * 16;
#pragma unroll
        for (int it = 0; it < 8; ++it) {
            int i = tid + it * 256;      // 2048 quads
            int r = i >> 4, q = i & 15;
            uint4 v = src[r * 16 + q];
            *(uint4*)(smp + r * AST_B + q * 16) = v;
        }
        if (tid < 17) *(uint4*)(smp + ZOFF + tid * 16) = make_uint4(0, 0, 0, 0);
    }

    // lane constants (fp8 k32 fragments have the b16-k16 footprint, 2 fp8/b16)
    const int t_ln = (lane & 7) + ((lane >> 3) & 1) * 8;   // A row-in-16
    const int kh_a = lane >> 4;                             // A 16B k-half
    const int n_ln = ((lane >> 4) << 3) + (lane & 7);       // B row-in-16
    const int kh_b = (lane >> 3) & 1;                       // B 16B k-half

    const unsigned char* Wl = g_w8 + (size_t)l * LL * DD * DD + (size_t)c0 * DD;

    float acc[4][4][4];
#pragma unroll
    for (int i = 0; i < 4; i++)
#pragma unroll
        for (int j = 0; j < 4; j++)
#pragma unroll
            for (int k = 0; k < 4; k++) acc[i][j][k] = 0.f;

    const int nch = (l + 1) * 2;       // (tap m) x (2 x 128B d-chunks)

    auto issueB = [&](int ch) {
        int m = ch >> 1, dk = ch & 1;
        const unsigned char* wb = Wl + (size_t)m * DD * DD + dk * 128;
        uint32_t sdst = sb + B_OFF0 + (ch % 3) * B_SZ;
#pragma unroll
        for (int it = 0; it < 4; ++it) {
            int i = tid + it * 256;      // 1024 x 16B
            int ci = i >> 3, q = i & 7;
            cpa16(sdst + ci * BST_B + q * 16, wb + (size_t)ci * DD + q * 16);
        }
        CP_COMMIT();
    };

    issueB(0);
    issueB(1);

    for (int ch = 0; ch < nch; ++ch) {
        if (ch == nch - 1) asm volatile("cp.async.wait_group 0;" ::: "memory");
        else               asm volatile("cp.async.wait_group 1;" ::: "memory");
        __syncthreads();
        if (ch + 2 < nch) issueB(ch + 2);

        const int m = ch >> 1, dk = ch & 1;
        const int srct = t_ln - m;
        const uint32_t bbase = sb + B_OFF0 + (ch % 3) * B_SZ;

        uint32_t arow[4];
#pragma unroll
        for (int mt = 0; mt < 4; ++mt) {
            int bl = warpM * 4 + mt;
            arow[mt] = (srct >= 0)
                ? sb + (uint32_t)((bl * 16 + srct) * AST_B + dk * 128 + kh_a * 16)
                : sb + (uint32_t)(ZOFF + dk * 128 + kh_a * 16);
        }

#pragma unroll
        for (int ks = 0; ks < 4; ++ks) {          // 4 x k32 = 128B chunk
            uint32_t a[4][4];
#pragma unroll
            for (int mt = 0; mt < 4; ++mt) ldsm4(a[mt], arow[mt] + ks * 32);
            uint32_t bfr[2][4];
#pragma unroll
            for (int n2 = 0; n2 < 2; ++n2) {
                uint32_t ba = bbase + (warpN * 32 + n2 * 16 + n_ln) * BST_B
                            + ks * 32 + kh_b * 16;
                ldsm4(bfr[n2], ba);
            }
#pragma unroll
            for (int mt = 0; mt < 4; ++mt)
#pragma unroll
                for (int ns = 0; ns < 4; ++ns)
                    mma_fp8(acc[mt][ns], a[mt],
                            bfr[ns >> 1][(ns & 1) * 2],
                            bfr[ns >> 1][(ns & 1) * 2 + 1]);
        }
        __syncthreads();
    }

    // ---- epilogue: two half-passes (64 rows each) through the A region ----
    const float inv = 1.0f / 4096.0f;     // undo 64*64 input scaling
    const int r  = lane >> 2;
    const int c2 = (lane & 3) * 2;
    for (int h = 0; h < 2; ++h) {
        if (warpM == h) {
#pragma unroll
            for (int mt = 0; mt < 4; ++mt)
#pragma unroll
                for (int ns = 0; ns < 4; ++ns) {
                    int row = mt * 16 + r;                    // local 0..63
                    int col = warpN * 32 + ns * 8 + c2;
                    float2* p0 = (float2*)(smp + (row)     * (EST_F * 4) + col * 4);
                    float2* p1 = (float2*)(smp + (row + 8) * (EST_F * 4) + col * 4);
                    *p0 = make_float2(acc[mt][ns][0], acc[mt][ns][1]);
                    *p1 = make_float2(acc[mt][ns][2], acc[mt][ns][3]);
                }
        }
        __syncthreads();
        const float* acc_s = (const float*)smp;
#pragma unroll
        for (int k = 0; k < 2; ++k) {
            int idx = tid + k * 256;          // 0..511
            int bbl = idx >> 7, cc = idx & 127;
            int b = b0 + h * 4 + bbl, c = c0 + cc;
            float bias = conv_b[l * DD + c];
            float h1 = 0.f, h2 = 0.f, h3 = 0.f, o = 0.f;
#pragma unroll
            for (int t = 0; t < TT; ++t) {
                float x = fmaf(acc_s[(bbl * 16 + t) * EST_F + cc], inv, bias);
                float xr = x > 0.f ? x : 0.f;
                float f = sigmoid_pos(xr);
                float e = g_emb[((size_t)b * TT + t) * DD + c];
                h1 = fmaf(f, e - h1, h1);
                h2 = fmaf(f, h1 - h2, h2);
                h3 = fmaf(f, h2 - h3, h3);
                o += h3;
            }
            g_opart[((size_t)l * BB + b) * DD + c] = o;
        }
        __syncthreads();
    }
}

// ---------------- 2) reduce over l -------------------------------------------
__global__ void reduce_o_kernel() {
    int idx = blockIdx.x * blockDim.x + threadIdx.x;
    float o = 0.f;
#pragma unroll
    for (int l = 0; l < LL; ++l) o += g_opart[(size_t)l * BB * DD + idx];
    g_o[idx] = o;
}

// ---------------- 3) z = [o, user_emb] @ fc1_w^T + fc1_b --------------------
__global__ void fc_kernel(const int* __restrict__ user_var,
                          const float* __restrict__ user_emb,
                          const float* __restrict__ fc1_w,
                          const float* __restrict__ fc1_b) {
    __shared__ float cat_s[8][2 * DD];
    int b0 = blockIdx.x * 8;
    int i0 = blockIdx.y * 8;
    int tid = threadIdx.x;
    for (int it = tid; it < 8 * (2 * DD / 4); it += 256) {
        int bb = it >> 7;
        int j4 = it & 127;
        float4 v;
        if (j4 < DD / 4)
            v = ((const float4*)(g_o + (size_t)(b0 + bb) * DD))[j4];
        else
            v = ((const float4*)(user_emb + (size_t)user_var[b0 + bb] * DD))[j4 - DD / 4];
        *(float4*)&cat_s[bb][j4 * 4] = v;
    }
    __syncthreads();
    int warp = tid >> 5, lane = tid & 31;
    int i = i0 + warp;
    float accv[8];
#pragma unroll
    for (int bb = 0; bb < 8; bb++) accv[bb] = 0.f;
    for (int j = lane; j < 2 * DD; j += 32) {
        float w = fc1_w[(size_t)i * (2 * DD) + j];
#pragma unroll
        for (int bb = 0; bb < 8; bb++) accv[bb] += w * cat_s[bb][j];
    }
#pragma unroll
    for (int bb = 0; bb < 8; bb++) {
        float v = accv[bb];
#pragma unroll
        for (int off = 16; off; off >>= 1) v += __shfl_down_sync(0xffffffffu, v, off);
        if (lane == 0) g_z[(size_t)(b0 + bb) * DD + i] = v + fc1_b[i];
    }
}

// ---------------- 4) res[b,n] = W2[item] . z[b] + b2 ------------------------
__global__ void out_kernel(const int* __restrict__ item_var,
                           const float* __restrict__ W2,
                           const float* __restrict__ b2,
                           float* __restrict__ out) {
    int gw = (blockIdx.x * blockDim.x + threadIdx.x) >> 5;
    int lane = threadIdx.x & 31;
    if (gw >= BB * NTGT) return;
    int b = gw >> 5;
    int iv = item_var[gw];
    const float* w = W2 + (size_t)iv * DD;
    const float* zz = g_z + (size_t)b * DD;
    float acc = 0.f;
    for (int d = lane; d < DD; d += 32) acc += w[d] * zz[d];
#pragma unroll
    for (int off = 16; off; off >>= 1) acc += __shfl_down_sync(0xffffffffu, acc, off);
    if (lane == 0) out[gw] = acc + b2[iv];
}

// ---------------- launch ------------------------------------------------------
extern "C" void kernel_launch(void* const* d_in, const int* in_sizes, int n_in,
                              void* d_out, int out_size) {
    const int*   seq_var  = (const int*)d_in[0];
    const int*   user_var = (const int*)d_in[1];
    const int*   item_var = (const int*)d_in[2];
    const float* item_emb = (const float*)d_in[3];
    const float* user_emb = (const float*)d_in[4];
    const float* conv_w   = (const float*)d_in[5];
    const float* conv_b   = (const float*)d_in[6];
    const float* fc1_w    = (const float*)d_in[7];
    const float* fc1_b    = (const float*)d_in[8];
    const float* W2       = (const float*)d_in[9];
    const float* b2       = (const float*)d_in[10];
    float* out = (float*)d_out;

    build_lut_kernel<<<1, 136>>>();
    gather_emb_kernel<<<NROW, 64>>>(seq_var, item_emb);
    {
        int* lut_ptr = nullptr;
        cudaGetSymbolAddress((void**)&lut_ptr, d_pair_lut);
        wconv_kernel<<<dim3(64, 136), 256>>>(conv_w, lut_ptr);
    }

    cudaFuncSetAttribute(conv_fused_kernel,
                         cudaFuncAttributeMaxDynamicSharedMemorySize, SMEM_REQ);
    conv_fused_kernel<<<dim3(2, BB / 8, LL), 256, SMEM_REQ>>>(conv_b);

    reduce_o_kernel<<<BB * DD / 256, 256>>>();
    fc_kernel<<<dim3(BB / 8, DD / 8), 256>>>(user_var, user_emb, fc1_w, fc1_b);
    out_kernel<<<(BB * NTGT * 32) / 256, 256>>>(item_var, W2, b2, out);
}

// round 6
// speedup vs baseline: 1.0692x; 1.0692x over previous
#include <cuda_runtime.h>
#include <cuda_bf16.h>
#include <math.h>
#include <stdint.h>

#define BB 512
#define TT 16
#define DD 256
#define LL 16
#define NTGT 32
#define NROW (BB*TT)

// ---------------- scratch (device globals) ----------------------------------
__device__ float         g_emb  [NROW*DD];             // fp32 emb    8 MB
__device__ unsigned char g_emb8 [NROW*DD];             // e4m3 emb*64 2 MB
__device__ unsigned char g_w8   [LL*LL*DD*DD];         // e4m3 w*64  16.7 MB
__device__ float         g_opart[LL*BB*DD];            // per-l o     8 MB
__device__ float         g_o    [BB*DD];
__device__ float         g_z    [BB*DD];

// ---------------- helpers ----------------------------------------------------
__device__ __forceinline__ uint32_t smem_u32(const void* p) {
    uint32_t a;
    asm("{ .reg .u64 t; cvta.to.shared.u64 t, %1; cvt.u32.u64 %0, t; }"
        : "=r"(a) : "l"(p));
    return a;
}
__device__ __forceinline__ void cpa16(uint32_t s, const void* g) {
    asm volatile("cp.async.cg.shared.global [%0], [%1], 16;"
                 :: "r"(s), "l"(g) : "memory");
}
#define CP_COMMIT() asm volatile("cp.async.commit_group;" ::: "memory")

__device__ __forceinline__ void ldsm4(uint32_t (&r)[4], uint32_t a) {
    asm volatile("ldmatrix.sync.aligned.m8n8.x4.shared.b16 {%0,%1,%2,%3}, [%4];"
                 : "=r"(r[0]), "=r"(r[1]), "=r"(r[2]), "=r"(r[3]) : "r"(a));
}
__device__ __forceinline__ void mma_fp8(float (&c)[4], const uint32_t (&a)[4],
                                        uint32_t b0, uint32_t b1) {
    asm volatile(
        "mma.sync.aligned.m16n8k32.row.col.f32.e4m3.e4m3.f32 "
        "{%0,%1,%2,%3}, {%4,%5,%6,%7}, {%8,%9}, {%0,%1,%2,%3};"
        : "+f"(c[0]), "+f"(c[1]), "+f"(c[2]), "+f"(c[3])
        : "r"(a[0]), "r"(a[1]), "r"(a[2]), "r"(a[3]), "r"(b0), "r"(b1));
}
__device__ __forceinline__ uint16_t cvt_e4m3x2(float hi, float lo) {
    uint16_t r;
    asm("cvt.rn.satfinite.e4m3x2.f32 %0, %1, %2;" : "=h"(r) : "f"(hi), "f"(lo));
    return r;
}
__device__ __forceinline__ float sigmoid_pos(float x) {
    if (x < 0.25f) {
        float x2 = x * x;
        float p = fmaf(x2, 1.0f / 480.0f, -1.0f / 48.0f);
        p = fmaf(x2, p, 0.25f);
        return fmaf(x, p, 0.5f);
    }
    return 1.0f / (1.0f + expf(-x));
}

// ---------------- 0a) gather item embeddings (fp32 + e4m3*64) ---------------
__global__ void gather_emb_kernel(const int* __restrict__ seq,
                                  const float* __restrict__ item_emb) {
    int row = blockIdx.x;
    int idx = seq[row];
    float4 v = ((const float4*)(item_emb + (size_t)idx * DD))[threadIdx.x];
    ((float4*)(g_emb + (size_t)row * DD))[threadIdx.x] = v;
    uint32_t p01 = cvt_e4m3x2(v.y * 64.f, v.x * 64.f);
    uint32_t p23 = cvt_e4m3x2(v.w * 64.f, v.z * 64.f);
    ((uint32_t*)g_emb8)[(size_t)row * 64 + threadIdx.x] = p01 | (p23 << 16);
}

// ---------------- 0b) conv_w fp32 -> e4m3*64 (valid pairs only) --------------
__device__ int d_pair_lut[136];
__global__ void build_lut_kernel() {
    int p = threadIdx.x;
    if (p < 136) {
        int l = 0, a = 0;
        while (a + l + 1 <= p) { a += l + 1; l++; }
        d_pair_lut[p] = l * 16 + (p - a);
    }
}
__global__ void wconv_kernel(const float* __restrict__ conv_w,
                             const int* __restrict__ pair_lut) {
    int p = blockIdx.y;
    int lm = pair_lut[p];
    size_t base = (size_t)lm * DD * DD;
    int i = blockIdx.x * 256 + threadIdx.x;
    float4 v = ((const float4*)(conv_w + base))[i];
    uint32_t p01 = cvt_e4m3x2(v.y * 64.f, v.x * 64.f);
    uint32_t p23 = cvt_e4m3x2(v.w * 64.f, v.z * 64.f);
    ((uint32_t*)(g_w8 + base))[i] = p01 | (p23 << 16);
}

// ---------------- 1) fused windowed fp8 GEMM + gate + QRNN -------------------
// CTA: l fixed, 8 b x 16 t x 128 c.  M-tile = 8 b's x 2 consecutive t (pair p);
// smem A row = t'*8 + bi (272B stride).  Tap m skips tiles with 2p+1 < m.
#define AST_B   272
#define BST_B   144
#define A_SZ    (128*AST_B)            // 34816
#define ZOFF    A_SZ
#define B_OFF0  (A_SZ + AST_B)         // 35088
#define B_SZ    (128*BST_B)            // 18432
#define SMEM_REQ (B_OFF0 + 4*B_SZ)     // 108816
#define EST_F   132                    // epilogue fp32 row stride (floats)

__global__ void __launch_bounds__(256, 2)
conv_fused_kernel(const float* __restrict__ conv_b) {
    extern __shared__ char smp[];
    const uint32_t sb = smem_u32(smp);
    const int tid = threadIdx.x, wid = tid >> 5, lane = tid & 31;
    const int warpM = wid >> 2, warpN = wid & 3;

    const int l  = 15 - blockIdx.z;
    const int b0 = blockIdx.y * 8;
    const int c0 = blockIdx.x * 128;

    // ---- stage A panel: row (t'*8+bi) <- emb8[b0+bi][t'], 256B payload ----
    {
#pragma unroll
        for (int it = 0; it < 8; ++it) {
            int i = tid + it * 256;          // 0..2047
            int r = i >> 4, q = i & 15;
            int tp = r >> 3, bi2 = r & 7;
            const uint4* src = (const uint4*)g_emb8
                             + ((size_t)(b0 + bi2) * TT + tp) * 16 + q;
            *(uint4*)(smp + r * AST_B + q * 16) = *src;
        }
        if (tid < 17) *(uint4*)(smp + ZOFF + tid * 16) = make_uint4(0, 0, 0, 0);
    }

    // lane constants
    const int t_ln = (lane & 7) + ((lane >> 3) & 1) * 8;   // A tile row 0..15
    const int ti   = t_ln >> 3;                             // t within pair
    const int bi   = t_ln & 7;                              // b within group
    const int kh_a = lane >> 4;
    const int n_ln = ((lane >> 4) << 3) + (lane & 7);
    const int kh_b = (lane >> 3) & 1;

    const unsigned char* Wl = g_w8 + (size_t)l * LL * DD * DD + (size_t)c0 * DD;

    float acc[4][4][4];
#pragma unroll
    for (int i = 0; i < 4; i++)
#pragma unroll
        for (int j = 0; j < 4; j++)
#pragma unroll
            for (int k = 0; k < 4; k++) acc[i][j][k] = 0.f;

    const int nch = (l + 1) * 2;

    auto issueB = [&](int ch) {
        int m = ch >> 1, dk = ch & 1;
        const unsigned char* wb = Wl + (size_t)m * DD * DD + dk * 128;
        uint32_t sdst = sb + B_OFF0 + (ch & 3) * B_SZ;
#pragma unroll
        for (int it = 0; it < 4; ++it) {
            int i = tid + it * 256;
            int ci = i >> 3, q = i & 7;
            cpa16(sdst + ci * BST_B + q * 16, wb + (size_t)ci * DD + q * 16);
        }
        CP_COMMIT();
    };

    issueB(0);
    issueB(1);
    if (nch > 2) issueB(2);

    for (int ch = 0; ch < nch; ++ch) {
        if (ch + 1 >= nch)      asm volatile("cp.async.wait_group 0;" ::: "memory");
        else if (ch + 2 >= nch) asm volatile("cp.async.wait_group 1;" ::: "memory");
        else                    asm volatile("cp.async.wait_group 2;" ::: "memory");
        __syncthreads();
        if (ch + 3 < nch) issueB(ch + 3);

        const int m = ch >> 1, dk = ch & 1;
        const uint32_t bbase = sb + B_OFF0 + (ch & 3) * B_SZ;

        bool val[4];
        uint32_t arow[4];
#pragma unroll
        for (int mt = 0; mt < 4; ++mt) {
            int pair = 2 * mt + warpM;
            val[mt] = (2 * pair + 1) >= m;
            int tp = 2 * pair + ti - m;
            arow[mt] = (tp >= 0)
                ? sb + (uint32_t)((tp * 8 + bi) * AST_B + dk * 128 + kh_a * 16)
                : sb + (uint32_t)(ZOFF + dk * 128 + kh_a * 16);
        }

#pragma unroll
        for (int ks = 0; ks < 4; ++ks) {
            uint32_t bfr[2][4];
#pragma unroll
            for (int n2 = 0; n2 < 2; ++n2) {
                uint32_t ba = bbase + (warpN * 32 + n2 * 16 + n_ln) * BST_B
                            + ks * 32 + kh_b * 16;
                ldsm4(bfr[n2], ba);
            }
#pragma unroll
            for (int mt = 0; mt < 4; ++mt) {
                if (!val[mt]) continue;
                uint32_t a[4];
                ldsm4(a, arow[mt] + ks * 32);
#pragma unroll
                for (int ns = 0; ns < 4; ++ns)
                    mma_fp8(acc[mt][ns], a,
                            bfr[ns >> 1][(ns & 1) * 2],
                            bfr[ns >> 1][(ns & 1) * 2 + 1]);
            }
        }
    }
    __syncthreads();

    // ---- epilogue: write ALL 128 rows (row = t*8 + b, 528B stride) ----
    {
        const int r0 = lane >> 2;          // = b lane of acc rows
        const int c2 = (lane & 3) * 2;
#pragma unroll
        for (int mt = 0; mt < 4; ++mt) {
            int pair = 2 * mt + warpM;
#pragma unroll
            for (int ns = 0; ns < 4; ++ns) {
                int col = warpN * 32 + ns * 8 + c2;
                float2* p0 = (float2*)(smp + ((2 * pair)     * 8 + r0) * (EST_F * 4) + col * 4);
                float2* p1 = (float2*)(smp + ((2 * pair + 1) * 8 + r0) * (EST_F * 4) + col * 4);
                *p0 = make_float2(acc[mt][ns][0], acc[mt][ns][1]);
                *p1 = make_float2(acc[mt][ns][2], acc[mt][ns][3]);
            }
        }
    }
    __syncthreads();

    // ---- gate + 3x fo-pool + t-sum: 4 sequential (b,c) items per thread ----
    const float inv = 1.0f / 4096.0f;
    const float* acc_s = (const float*)smp;
#pragma unroll
    for (int k = 0; k < 4; ++k) {
        int idx = tid + k * 256;           // 0..1023
        int bbl = idx >> 7, cc = idx & 127;
        int b = b0 + bbl, c = c0 + cc;
        float bias = conv_b[l * DD + c];
        float h1 = 0.f, h2 = 0.f, h3 = 0.f, o = 0.f;
#pragma unroll
        for (int t = 0; t < TT; ++t) {
            float x = fmaf(acc_s[(t * 8 + bbl) * EST_F + cc], inv, bias);
            float xr = x > 0.f ? x : 0.f;
            float f = sigmoid_pos(xr);
            float e = g_emb[((size_t)b * TT + t) * DD + c];
            h1 = fmaf(f, e - h1, h1);
            h2 = fmaf(f, h1 - h2, h2);
            h3 = fmaf(f, h2 - h3, h3);
            o += h3;
        }
        g_opart[((size_t)l * BB + b) * DD + c] = o;
    }
}

// ---------------- 2) reduce over l -------------------------------------------
__global__ void reduce_o_kernel() {
    int idx = blockIdx.x * blockDim.x + threadIdx.x;
    float o = 0.f;
#pragma unroll
    for (int l = 0; l < LL; ++l) o += g_opart[(size_t)l * BB * DD + idx];
    g_o[idx] = o;
}

// ---------------- 3) z = [o, user_emb] @ fc1_w^T + fc1_b --------------------
__global__ void fc_kernel(const int* __restrict__ user_var,
                          const float* __restrict__ user_emb,
                          const float* __restrict__ fc1_w,
                          const float* __restrict__ fc1_b) {
    __shared__ float cat_s[8][2 * DD];
    int b0 = blockIdx.x * 8;
    int i0 = blockIdx.y * 8;
    int tid = threadIdx.x;
    for (int it = tid; it < 8 * (2 * DD / 4); it += 256) {
        int bb = it >> 7;
        int j4 = it & 127;
        float4 v;
        if (j4 < DD / 4)
            v = ((const float4*)(g_o + (size_t)(b0 + bb) * DD))[j4];
        else
            v = ((const float4*)(user_emb + (size_t)user_var[b0 + bb] * DD))[j4 - DD / 4];
        *(float4*)&cat_s[bb][j4 * 4] = v;
    }
    __syncthreads();
    int warp = tid >> 5, lane = tid & 31;
    int i = i0 + warp;
    float accv[8];
#pragma unroll
    for (int bb = 0; bb < 8; bb++) accv[bb] = 0.f;
    for (int j = lane; j < 2 * DD; j += 32) {
        float w = fc1_w[(size_t)i * (2 * DD) + j];
#pragma unroll
        for (int bb = 0; bb < 8; bb++) accv[bb] += w * cat_s[bb][j];
    }
#pragma unroll
    for (int bb = 0; bb < 8; bb++) {
        float v = accv[bb];
#pragma unroll
        for (int off = 16; off; off >>= 1) v += __shfl_down_sync(0xffffffffu, v, off);
        if (lane == 0) g_z[(size_t)(b0 + bb) * DD + i] = v + fc1_b[i];
    }
}

// ---------------- 4) res[b,n] = W2[item] . z[b] + b2 ------------------------
__global__ void out_kernel(const int* __restrict__ item_var,
                           const float* __restrict__ W2,
                           const float* __restrict__ b2,
                           float* __restrict__ out) {
    int gw = (blockIdx.x * blockDim.x + threadIdx.x) >> 5;
    int lane = threadIdx.x & 31;
    if (gw >= BB * NTGT) return;
    int b = gw >> 5;
    int iv = item_var[gw];
    const float* w = W2 + (size_t)iv * DD;
    const float* zz = g_z + (size_t)b * DD;
    float acc = 0.f;
    for (int d = lane; d < DD; d += 32) acc += w[d] * zz[d];
#pragma unroll
    for (int off = 16; off; off >>= 1) acc += __shfl_down_sync(0xffffffffu, acc, off);
    if (lane == 0) out[gw] = acc + b2[iv];
}

// ---------------- launch ------------------------------------------------------
extern "C" void kernel_launch(void* const* d_in, const int* in_sizes, int n_in,
                              void* d_out, int out_size) {
    const int*   seq_var  = (const int*)d_in[0];
    const int*   user_var = (const int*)d_in[1];
    const int*   item_var = (const int*)d_in[2];
    const float* item_emb = (const float*)d_in[3];
    const float* user_emb = (const float*)d_in[4];
    const float* conv_w   = (const float*)d_in[5];
    const float* conv_b   = (const float*)d_in[6];
    const float* fc1_w    = (const float*)d_in[7];
    const float* fc1_b    = (const float*)d_in[8];
    const float* W2       = (const float*)d_in[9];
    const float* b2       = (const float*)d_in[10];
    float* out = (float*)d_out;

    build_lut_kernel<<<1, 136>>>();
    gather_emb_kernel<<<NROW, 64>>>(seq_var, item_emb);
    {
        int* lut_ptr = nullptr;
        cudaGetSymbolAddress((void**)&lut_ptr, d_pair_lut);
        wconv_kernel<<<dim3(64, 136), 256>>>(conv_w, lut_ptr);
    }

    cudaFuncSetAttribute(conv_fused_kernel,
                         cudaFuncAttributeMaxDynamicSharedMemorySize, SMEM_REQ);
    conv_fused_kernel<<<dim3(2, BB / 8, LL), 256, SMEM_REQ>>>(conv_b);

    reduce_o_kernel<<<BB * DD / 256, 256>>>();
    fc_kernel<<<dim3(BB / 8, DD / 8), 256>>>(user_var, user_emb, fc1_w, fc1_b);
    out_kernel<<<(BB * NTGT * 32) / 256, 256>>>(item_var, W2, b2, out);
}

// round 7
// speedup vs baseline: 1.1323x; 1.0590x over previous
#include <cuda_runtime.h>
#include <cuda_bf16.h>
#include <math.h>
#include <stdint.h>

#define BB 512
#define TT 16
#define DD 256
#define LL 16
#define NTGT 32
#define NROW (BB*TT)

// ---------------- scratch (device globals) ----------------------------------
__device__ float         g_emb  [NROW*DD];             // fp32 emb    8 MB
__device__ unsigned char g_emb8 [NROW*DD];             // e4m3 emb*64 2 MB
__device__ unsigned char g_w8   [LL*LL*DD*DD];         // e4m3 w*64  16.7 MB
__device__ float         g_opart[LL*BB*DD];            // per-l o     8 MB
__device__ float         g_o    [BB*DD];
__device__ float         g_z    [BB*DD];

// ---------------- helpers ----------------------------------------------------
__device__ __forceinline__ uint32_t smem_u32(const void* p) {
    uint32_t a;
    asm("{ .reg .u64 t; cvta.to.shared.u64 t, %1; cvt.u32.u64 %0, t; }"
        : "=r"(a) : "l"(p));
    return a;
}
__device__ __forceinline__ void cpa16(uint32_t s, const void* g) {
    asm volatile("cp.async.cg.shared.global [%0], [%1], 16;"
                 :: "r"(s), "l"(g) : "memory");
}
#define CP_COMMIT() asm volatile("cp.async.commit_group;" ::: "memory")

__device__ __forceinline__ void ldsm4(uint32_t (&r)[4], uint32_t a) {
    asm volatile("ldmatrix.sync.aligned.m8n8.x4.shared.b16 {%0,%1,%2,%3}, [%4];"
                 : "=r"(r[0]), "=r"(r[1]), "=r"(r[2]), "=r"(r[3]) : "r"(a));
}
__device__ __forceinline__ void mma_fp8(float (&c)[4], const uint32_t (&a)[4],
                                        uint32_t b0, uint32_t b1) {
    asm volatile(
        "mma.sync.aligned.m16n8k32.row.col.f32.e4m3.e4m3.f32 "
        "{%0,%1,%2,%3}, {%4,%5,%6,%7}, {%8,%9}, {%0,%1,%2,%3};"
        : "+f"(c[0]), "+f"(c[1]), "+f"(c[2]), "+f"(c[3])
        : "r"(a[0]), "r"(a[1]), "r"(a[2]), "r"(a[3]), "r"(b0), "r"(b1));
}
__device__ __forceinline__ uint16_t cvt_e4m3x2(float hi, float lo) {
    uint16_t r;
    asm("cvt.rn.satfinite.e4m3x2.f32 %0, %1, %2;" : "=h"(r) : "f"(hi), "f"(lo));
    return r;
}
__device__ __forceinline__ float sigmoid_pos(float x) {
    if (x < 0.25f) {
        float x2 = x * x;
        float p = fmaf(x2, 1.0f / 480.0f, -1.0f / 48.0f);
        p = fmaf(x2, p, 0.25f);
        return fmaf(x, p, 0.5f);
    }
    return 1.0f / (1.0f + expf(-x));
}

// ---------------- 0a) gather item embeddings (fp32 + e4m3*64) ---------------
__global__ void gather_emb_kernel(const int* __restrict__ seq,
                                  const float* __restrict__ item_emb) {
    int row = blockIdx.x;
    int idx = seq[row];
    float4 v = ((const float4*)(item_emb + (size_t)idx * DD))[threadIdx.x];
    ((float4*)(g_emb + (size_t)row * DD))[threadIdx.x] = v;
    uint32_t p01 = cvt_e4m3x2(v.y * 64.f, v.x * 64.f);
    uint32_t p23 = cvt_e4m3x2(v.w * 64.f, v.z * 64.f);
    ((uint32_t*)g_emb8)[(size_t)row * 64 + threadIdx.x] = p01 | (p23 << 16);
}

// ---------------- 0b) conv_w fp32 -> e4m3*64 (valid pairs only) --------------
__device__ int d_pair_lut[136];
__global__ void build_lut_kernel() {
    int p = threadIdx.x;
    if (p < 136) {
        int l = 0, a = 0;
        while (a + l + 1 <= p) { a += l + 1; l++; }
        d_pair_lut[p] = l * 16 + (p - a);
    }
}
__global__ void wconv_kernel(const float* __restrict__ conv_w,
                             const int* __restrict__ pair_lut) {
    int p = blockIdx.y;
    int lm = pair_lut[p];
    size_t base = (size_t)lm * DD * DD;
    int i = blockIdx.x * 256 + threadIdx.x;
    float4 v = ((const float4*)(conv_w + base))[i];
    uint32_t p01 = cvt_e4m3x2(v.y * 64.f, v.x * 64.f);
    uint32_t p23 = cvt_e4m3x2(v.w * 64.f, v.z * 64.f);
    ((uint32_t*)(g_w8 + base))[i] = p01 | (p23 << 16);
}

// ---------------- 1) fused windowed fp8 GEMM + gate + QRNN -------------------
// CTA: l fixed, 8 b x 16 t (M=128, tile = 8b x 2t pair) x 64 c.
// Warps: warpM 0..3 x warpN 0..1; warp owns pairs {warpM, warpM+4}, 32 c.
// Tap m skips M-tiles with 2*pair+1 < m.
#define AST_B   272
#define BST_B   144
#define A_SZ    (128*AST_B)            // 34816
#define ZOFF    A_SZ
#define B_OFF0  (A_SZ + AST_B)         // 35088
#define B_SZ    (64*BST_B)             // 9216
#define SMEM_REQ (B_OFF0 + 4*B_SZ)     // 71952
#define EST_F   68                     // epilogue fp32 row stride (= 272B)

__global__ void __launch_bounds__(256, 3)
conv_fused_kernel(const float* __restrict__ conv_b) {
    extern __shared__ char smp[];
    const uint32_t sb = smem_u32(smp);
    const int tid = threadIdx.x, wid = tid >> 5, lane = tid & 31;
    const int warpM = wid >> 1, warpN = wid & 1;

    const int l  = 15 - blockIdx.z;
    const int b0 = blockIdx.y * 8;
    const int c0 = blockIdx.x * 64;

    // ---- stage A panel: row (t'*8+bi) <- emb8[b0+bi][t'], 256B payload ----
    {
#pragma unroll
        for (int it = 0; it < 8; ++it) {
            int i = tid + it * 256;          // 0..2047
            int r = i >> 4, q = i & 15;
            int tp = r >> 3, bi2 = r & 7;
            const uint4* src = (const uint4*)g_emb8
                             + ((size_t)(b0 + bi2) * TT + tp) * 16 + q;
            *(uint4*)(smp + r * AST_B + q * 16) = *src;
        }
        if (tid < 17) *(uint4*)(smp + ZOFF + tid * 16) = make_uint4(0, 0, 0, 0);
    }

    // lane constants
    const int t_ln = (lane & 7) + ((lane >> 3) & 1) * 8;   // A tile row 0..15
    const int ti   = t_ln >> 3;                             // t within pair
    const int bi   = t_ln & 7;                              // b within group
    const int kh_a = lane >> 4;
    const int n_ln = ((lane >> 4) << 3) + (lane & 7);
    const int kh_b = (lane >> 3) & 1;

    const unsigned char* Wl = g_w8 + (size_t)l * LL * DD * DD + (size_t)c0 * DD;

    float acc[2][4][4];
#pragma unroll
    for (int i = 0; i < 2; i++)
#pragma unroll
        for (int j = 0; j < 4; j++)
#pragma unroll
            for (int k = 0; k < 4; k++) acc[i][j][k] = 0.f;

    const int nch = (l + 1) * 2;

    auto issueB = [&](int ch) {
        int m = ch >> 1, dk = ch & 1;
        const unsigned char* wb = Wl + (size_t)m * DD * DD + dk * 128;
        uint32_t sdst = sb + B_OFF0 + (ch & 3) * B_SZ;
#pragma unroll
        for (int it = 0; it < 2; ++it) {
            int i = tid + it * 256;          // 512 x 16B
            int ci = i >> 3, q = i & 7;
            cpa16(sdst + ci * BST_B + q * 16, wb + (size_t)ci * DD + q * 16);
        }
        CP_COMMIT();
    };

    issueB(0);
    issueB(1);
    if (nch > 2) issueB(2);

    for (int ch = 0; ch < nch; ++ch) {
        if (ch + 1 >= nch)      asm volatile("cp.async.wait_group 0;" ::: "memory");
        else if (ch + 2 >= nch) asm volatile("cp.async.wait_group 1;" ::: "memory");
        else                    asm volatile("cp.async.wait_group 2;" ::: "memory");
        __syncthreads();
        if (ch + 3 < nch) issueB(ch + 3);

        const int m = ch >> 1, dk = ch & 1;
        const uint32_t bbase = sb + B_OFF0 + (ch & 3) * B_SZ;

        bool val[2];
        uint32_t arow[2];
#pragma unroll
        for (int mt = 0; mt < 2; ++mt) {
            int pair = warpM + 4 * mt;
            val[mt] = (2 * pair + 1) >= m;
            int tp = 2 * pair + ti - m;
            arow[mt] = (tp >= 0)
                ? sb + (uint32_t)((tp * 8 + bi) * AST_B + dk * 128 + kh_a * 16)
                : sb + (uint32_t)(ZOFF + dk * 128 + kh_a * 16);
        }

#pragma unroll
        for (int ks = 0; ks < 4; ++ks) {
            uint32_t bfr[2][4];
#pragma unroll
            for (int n2 = 0; n2 < 2; ++n2) {
                uint32_t ba = bbase + (warpN * 32 + n2 * 16 + n_ln) * BST_B
                            + ks * 32 + kh_b * 16;
                ldsm4(bfr[n2], ba);
            }
#pragma unroll
            for (int mt = 0; mt < 2; ++mt) {
                if (!val[mt]) continue;
                uint32_t a[4];
                ldsm4(a, arow[mt] + ks * 32);
#pragma unroll
                for (int ns = 0; ns < 4; ++ns)
                    mma_fp8(acc[mt][ns], a,
                            bfr[ns >> 1][(ns & 1) * 2],
                            bfr[ns >> 1][(ns & 1) * 2 + 1]);
            }
        }
    }
    __syncthreads();

    // ---- epilogue: write all 128 rows (row = t*8 + b), 64 c, 272B stride ----
    {
        const int r0 = lane >> 2;          // b lane of acc rows
        const int c2 = (lane & 3) * 2;
#pragma unroll
        for (int mt = 0; mt < 2; ++mt) {
            int pair = warpM + 4 * mt;
#pragma unroll
            for (int ns = 0; ns < 4; ++ns) {
                int col = warpN * 32 + ns * 8 + c2;
                float2* p0 = (float2*)(smp + ((2 * pair)     * 8 + r0) * (EST_F * 4) + col * 4);
                float2* p1 = (float2*)(smp + ((2 * pair + 1) * 8 + r0) * (EST_F * 4) + col * 4);
                *p0 = make_float2(acc[mt][ns][0], acc[mt][ns][1]);
                *p1 = make_float2(acc[mt][ns][2], acc[mt][ns][3]);
            }
        }
    }
    __syncthreads();

    // ---- gate + 3x fo-pool + t-sum: 2 sequential (b,c) items per thread ----
    const float inv = 1.0f / 4096.0f;
    const float* acc_s = (const float*)smp;
#pragma unroll
    for (int k = 0; k < 2; ++k) {
        int idx = tid + k * 256;           // 0..511
        int bbl = idx >> 6, cc = idx & 63;
        int b = b0 + bbl, c = c0 + cc;
        float bias = conv_b[l * DD + c];
        float h1 = 0.f, h2 = 0.f, h3 = 0.f, o = 0.f;
#pragma unroll
        for (int t = 0; t < TT; ++t) {
            float x = fmaf(acc_s[(t * 8 + bbl) * EST_F + cc], inv, bias);
            float xr = x > 0.f ? x : 0.f;
            float f = sigmoid_pos(xr);
            float e = g_emb[((size_t)b * TT + t) * DD + c];
            h1 = fmaf(f, e - h1, h1);
            h2 = fmaf(f, h1 - h2, h2);
            h3 = fmaf(f, h2 - h3, h3);
            o += h3;
        }
        g_opart[((size_t)l * BB + b) * DD + c] = o;
    }
}

// ---------------- 2) reduce over l -------------------------------------------
__global__ void reduce_o_kernel() {
    int idx = blockIdx.x * blockDim.x + threadIdx.x;
    float o = 0.f;
#pragma unroll
    for (int l = 0; l < LL; ++l) o += g_opart[(size_t)l * BB * DD + idx];
    g_o[idx] = o;
}

// ---------------- 3) z = [o, user_emb] @ fc1_w^T + fc1_b --------------------
__global__ void fc_kernel(const int* __restrict__ user_var,
                          const float* __restrict__ user_emb,
                          const float* __restrict__ fc1_w,
                          const float* __restrict__ fc1_b) {
    __shared__ float cat_s[8][2 * DD];
    int b0 = blockIdx.x * 8;
    int i0 = blockIdx.y * 8;
    int tid = threadIdx.x;
    for (int it = tid; it < 8 * (2 * DD / 4); it += 256) {
        int bb = it >> 7;
        int j4 = it & 127;
        float4 v;
        if (j4 < DD / 4)
            v = ((const float4*)(g_o + (size_t)(b0 + bb) * DD))[j4];
        else
            v = ((const float4*)(user_emb + (size_t)user_var[b0 + bb] * DD))[j4 - DD / 4];
        *(float4*)&cat_s[bb][j4 * 4] = v;
    }
    __syncthreads();
    int warp = tid >> 5, lane = tid & 31;
    int i = i0 + warp;
    float accv[8];
#pragma unroll
    for (int bb = 0; bb < 8; bb++) accv[bb] = 0.f;
    for (int j = lane; j < 2 * DD; j += 32) {
        float w = fc1_w[(size_t)i * (2 * DD) + j];
#pragma unroll
        for (int bb = 0; bb < 8; bb++) accv[bb] += w * cat_s[bb][j];
    }
#pragma unroll
    for (int bb = 0; bb < 8; bb++) {
        float v = accv[bb];
#pragma unroll
        for (int off = 16; off; off >>= 1) v += __shfl_down_sync(0xffffffffu, v, off);
        if (lane == 0) g_z[(size_t)(b0 + bb) * DD + i] = v + fc1_b[i];
    }
}

// ---------------- 4) res[b,n] = W2[item] . z[b] + b2 ------------------------
__global__ void out_kernel(const int* __restrict__ item_var,
                           const float* __restrict__ W2,
                           const float* __restrict__ b2,
                           float* __restrict__ out) {
    int gw = (blockIdx.x * blockDim.x + threadIdx.x) >> 5;
    int lane = threadIdx.x & 31;
    if (gw >= BB * NTGT) return;
    int b = gw >> 5;
    int iv = item_var[gw];
    const float* w = W2 + (size_t)iv * DD;
    const float* zz = g_z + (size_t)b * DD;
    float acc = 0.f;
    for (int d = lane; d < DD; d += 32) acc += w[d] * zz[d];
#pragma unroll
    for (int off = 16; off; off >>= 1) acc += __shfl_down_sync(0xffffffffu, acc, off);
    if (lane == 0) out[gw] = acc + b2[iv];
}

// ---------------- launch ------------------------------------------------------
extern "C" void kernel_launch(void* const* d_in, const int* in_sizes, int n_in,
                              void* d_out, int out_size) {
    const int*   seq_var  = (const int*)d_in[0];
    const int*   user_var = (const int*)d_in[1];
    const int*   item_var = (const int*)d_in[2];
    const float* item_emb = (const float*)d_in[3];
    const float* user_emb = (const float*)d_in[4];
    const float* conv_w   = (const float*)d_in[5];
    const float* conv_b   = (const float*)d_in[6];
    const float* fc1_w    = (const float*)d_in[7];
    const float* fc1_b    = (const float*)d_in[8];
    const float* W2       = (const float*)d_in[9];
    const float* b2       = (const float*)d_in[10];
    float* out = (float*)d_out;

    build_lut_kernel<<<1, 136>>>();
    gather_emb_kernel<<<NROW, 64>>>(seq_var, item_emb);
    {
        int* lut_ptr = nullptr;
        cudaGetSymbolAddress((void**)&lut_ptr, d_pair_lut);
        wconv_kernel<<<dim3(64, 136), 256>>>(conv_w, lut_ptr);
    }

    cudaFuncSetAttribute(conv_fused_kernel,
                         cudaFuncAttributeMaxDynamicSharedMemorySize, SMEM_REQ);
    conv_fused_kernel<<<dim3(4, BB / 8, LL), 256, SMEM_REQ>>>(conv_b);

    reduce_o_kernel<<<BB * DD / 256, 256>>>();
    fc_kernel<<<dim3(BB / 8, DD / 8), 256>>>(user_var, user_emb, fc1_w, fc1_b);
    out_kernel<<<(BB * NTGT * 32) / 256, 256>>>(item_var, W2, b2, out);
}

// round 10
// speedup vs baseline: 1.1597x; 1.0242x over previous
#include <cuda_runtime.h>
#include <cuda_bf16.h>
#include <math.h>
#include <stdint.h>

#define BB 512
#define TT 16
#define DD 256
#define LL 16
#define NTGT 32
#define NROW (BB*TT)

// ---------------- scratch (device globals) ----------------------------------
__device__ float         g_emb  [NROW*DD];             // fp32 emb    8 MB
__device__ unsigned char g_emb8 [NROW*DD];             // e4m3 emb*64 2 MB
__device__ unsigned char g_w8   [LL*LL*DD*DD];         // e4m3 w*64  16.7 MB
__device__ float         g_opart[LL*BB*DD];            // per-l o     8 MB
__device__ float         g_o    [BB*DD];
__device__ float         g_z    [BB*DD];

// ---------------- helpers ----------------------------------------------------
__device__ __forceinline__ uint32_t smem_u32(const void* p) {
    uint32_t a;
    asm("{ .reg .u64 t; cvta.to.shared.u64 t, %1; cvt.u32.u64 %0, t; }"
        : "=r"(a) : "l"(p));
    return a;
}
__device__ __forceinline__ void cpa16(uint32_t s, const void* g) {
    asm volatile("cp.async.cg.shared.global [%0], [%1], 16;"
                 :: "r"(s), "l"(g) : "memory");
}
#define CP_COMMIT() asm volatile("cp.async.commit_group;" ::: "memory")

__device__ __forceinline__ void ldsm4(uint32_t (&r)[4], uint32_t a) {
    asm volatile("ldmatrix.sync.aligned.m8n8.x4.shared.b16 {%0,%1,%2,%3}, [%4];"
                 : "=r"(r[0]), "=r"(r[1]), "=r"(r[2]), "=r"(r[3]) : "r"(a));
}
__device__ __forceinline__ void mma_fp8(float (&c)[4], const uint32_t (&a)[4],
                                        uint32_t b0, uint32_t b1) {
    asm volatile(
        "mma.sync.aligned.m16n8k32.row.col.f32.e4m3.e4m3.f32 "
        "{%0,%1,%2,%3}, {%4,%5,%6,%7}, {%8,%9}, {%0,%1,%2,%3};"
        : "+f"(c[0]), "+f"(c[1]), "+f"(c[2]), "+f"(c[3])
        : "r"(a[0]), "r"(a[1]), "r"(a[2]), "r"(a[3]), "r"(b0), "r"(b1));
}
__device__ __forceinline__ uint16_t cvt_e4m3x2(float hi, float lo) {
    uint16_t r;
    asm("cvt.rn.satfinite.e4m3x2.f32 %0, %1, %2;" : "=h"(r) : "f"(hi), "f"(lo));
    return r;
}
__device__ __forceinline__ float sigmoid_pos(float x) {
    if (x < 0.25f) {
        float x2 = x * x;
        float p = fmaf(x2, 1.0f / 480.0f, -1.0f / 48.0f);
        p = fmaf(x2, p, 0.25f);
        return fmaf(x, p, 0.5f);
    }
    return 1.0f / (1.0f + expf(-x));
}

// ---------------- 0a) gather item embeddings (fp32 + e4m3*64) ---------------
__global__ void gather_emb_kernel(const int* __restrict__ seq,
                                  const float* __restrict__ item_emb) {
    int row = blockIdx.x;
    int idx = seq[row];
    float4 v = ((const float4*)(item_emb + (size_t)idx * DD))[threadIdx.x];
    ((float4*)(g_emb + (size_t)row * DD))[threadIdx.x] = v;
    uint32_t p01 = cvt_e4m3x2(v.y * 64.f, v.x * 64.f);
    uint32_t p23 = cvt_e4m3x2(v.w * 64.f, v.z * 64.f);
    ((uint32_t*)g_emb8)[(size_t)row * 64 + threadIdx.x] = p01 | (p23 << 16);
}

// ---------------- 0b) conv_w fp32 -> e4m3*64 (valid pairs only) --------------
__device__ int d_pair_lut[136];
__global__ void build_lut_kernel() {
    int p = threadIdx.x;
    if (p < 136) {
        int l = 0, a = 0;
        while (a + l + 1 <= p) { a += l + 1; l++; }
        d_pair_lut[p] = l * 16 + (p - a);
    }
}
__global__ void wconv_kernel(const float* __restrict__ conv_w,
                             const int* __restrict__ pair_lut) {
    int p = blockIdx.y;
    int lm = pair_lut[p];
    size_t base = (size_t)lm * DD * DD;
    int i = blockIdx.x * 256 + threadIdx.x;
    float4 v = ((const float4*)(conv_w + base))[i];
    uint32_t p01 = cvt_e4m3x2(v.y * 64.f, v.x * 64.f);
    uint32_t p23 = cvt_e4m3x2(v.w * 64.f, v.z * 64.f);
    ((uint32_t*)(g_w8 + base))[i] = p01 | (p23 << 16);
}

// ---------------- 1) fused windowed fp8 GEMM + gate + QRNN -------------------
// CTA: l fixed, 8 b x 16 t (M=128, tile = 8b x 2t pair) x 64 c.
// Chunk = one tap m: full 256B of K, ring-2 B buffers.
// Warps: warpM 0..3 x warpN 0..1; warp owns pairs {warpM, warpM+4}, 32 c.
#define AST_B   272
#define A_SZ    (128*AST_B)            // 34816
#define ZOFF    A_SZ
#define B_OFF0  (A_SZ + AST_B)         // 35088
#define B_SZ    (64*AST_B)             // 17408 (64 rows x 272B, 256B payload)
#define SMEM_REQ (B_OFF0 + 2*B_SZ)     // 69904
#define EST_F   68                     // epilogue fp32 row stride (= 272B)

__global__ void __launch_bounds__(256, 3)
conv_fused_kernel(const float* __restrict__ conv_b) {
    extern __shared__ char smp[];
    const uint32_t sb = smem_u32(smp);
    const int tid = threadIdx.x, wid = tid >> 5, lane = tid & 31;
    const int warpM = wid >> 1, warpN = wid & 1;

    const int l  = 15 - blockIdx.z;
    const int b0 = blockIdx.y * 8;
    const int c0 = blockIdx.x * 64;

    // ---- stage A panel: row (t'*8+bi) <- emb8[b0+bi][t'], 256B payload ----
    {
#pragma unroll
        for (int it = 0; it < 8; ++it) {
            int i = tid + it * 256;          // 0..2047
            int r = i >> 4, q = i & 15;
            int tp = r >> 3, bi2 = r & 7;
            const uint4* src = (const uint4*)g_emb8
                             + ((size_t)(b0 + bi2) * TT + tp) * 16 + q;
            *(uint4*)(smp + r * AST_B + q * 16) = *src;
        }
        if (tid < 17) *(uint4*)(smp + ZOFF + tid * 16) = make_uint4(0, 0, 0, 0);
    }

    // lane constants
    const int t_ln = (lane & 7) + ((lane >> 3) & 1) * 8;   // A tile row 0..15
    const int ti   = t_ln >> 3;                             // t within pair
    const int bi   = t_ln & 7;                              // b within group
    const int kh_a = lane >> 4;
    const int n_ln = ((lane >> 4) << 3) + (lane & 7);
    const int kh_b = (lane >> 3) & 1;

    const unsigned char* Wl = g_w8 + (size_t)l * LL * DD * DD + (size_t)c0 * DD;

    float acc[2][4][4];
#pragma unroll
    for (int i = 0; i < 2; i++)
#pragma unroll
        for (int j = 0; j < 4; j++)
#pragma unroll
            for (int k = 0; k < 4; k++) acc[i][j][k] = 0.f;

    const int nch = l + 1;

    // B chunk = tap m: 64 c-rows x 256B
    auto issueB = [&](int m) {
        const unsigned char* wb = Wl + (size_t)m * DD * DD;
        uint32_t sdst = sb + B_OFF0 + (m & 1) * B_SZ;
#pragma unroll
        for (int it = 0; it < 4; ++it) {
            int i = tid + it * 256;          // 1024 x 16B
            int ci = i >> 4, q = i & 15;
            cpa16(sdst + ci * AST_B + q * 16, wb + (size_t)ci * DD + q * 16);
        }
        CP_COMMIT();
    };

    issueB(0);
    if (nch > 1) issueB(1);

    // per-warp/lane B ldsm bases (offset within a buffer)
    const uint32_t boff0 = (uint32_t)((warpN * 32 + n_ln) * AST_B + kh_b * 16);
    const uint32_t boff1 = boff0 + 16 * AST_B;

    for (int m = 0; m < nch; ++m) {
        if (m + 1 < nch) asm volatile("cp.async.wait_group 1;" ::: "memory");
        else             asm volatile("cp.async.wait_group 0;" ::: "memory");
        __syncthreads();
        if (m + 2 < nch) issueB(m + 2);

        const int p0 = warpM, p1 = warpM + 4;
        const bool v0 = (2 * p0 + 1) >= m;         // v1 is true whenever v0 can be false
        const bool v1 = (2 * p1 + 1) >= m;
        if (!v0 && !v1) continue;

        const uint32_t bbase = sb + B_OFF0 + (m & 1) * B_SZ;
        const uint32_t b_ld0 = bbase + boff0;
        const uint32_t b_ld1 = bbase + boff1;

        uint32_t arow[2];
        bool val[2] = {v0, v1};
        {
            int tp0 = 2 * p0 + ti - m;
            int tp1 = 2 * p1 + ti - m;
            arow[0] = (tp0 >= 0)
                ? sb + (uint32_t)((tp0 * 8 + bi) * AST_B + kh_a * 16)
                : sb + (uint32_t)(ZOFF + kh_a * 16);
            arow[1] = (tp1 >= 0)
                ? sb + (uint32_t)((tp1 * 8 + bi) * AST_B + kh_a * 16)
                : sb + (uint32_t)(ZOFF + kh_a * 16);
        }

#pragma unroll
        for (int ks = 0; ks < 8; ++ks) {           // 8 x k32 = 256B
            uint32_t bfr[2][4];
            ldsm4(bfr[0], b_ld0 + ks * 32);
            ldsm4(bfr[1], b_ld1 + ks * 32);
#pragma unroll
            for (int mt = 0; mt < 2; ++mt) {
                if (!val[mt]) continue;
                uint32_t a[4];
                ldsm4(a, arow[mt] + ks * 32);
#pragma unroll
                for (int ns = 0; ns < 4; ++ns)
                    mma_fp8(acc[mt][ns], a,
                            bfr[ns >> 1][(ns & 1) * 2],
                            bfr[ns >> 1][(ns & 1) * 2 + 1]);
            }
        }
    }
    __syncthreads();

    // ---- epilogue: write all 128 rows (row = t*8 + b), 64 c, 272B stride ----
    {
        const int r0 = lane >> 2;          // b lane of acc rows
        const int c2 = (lane & 3) * 2;
#pragma unroll
        for (int mt = 0; mt < 2; ++mt) {
            int pair = warpM + 4 * mt;
#pragma unroll
            for (int ns = 0; ns < 4; ++ns) {
                int col = warpN * 32 + ns * 8 + c2;
                float2* p0 = (float2*)(smp + ((2 * pair)     * 8 + r0) * (EST_F * 4) + col * 4);
                float2* p1 = (float2*)(smp + ((2 * pair + 1) * 8 + r0) * (EST_F * 4) + col * 4);
                *p0 = make_float2(acc[mt][ns][0], acc[mt][ns][1]);
                *p1 = make_float2(acc[mt][ns][2], acc[mt][ns][3]);
            }
        }
    }
    __syncthreads();

    // ---- gate + 3x fo-pool + t-sum: 2 sequential (b,c) items per thread ----
    const float inv = 1.0f / 4096.0f;
    const float* acc_s = (const float*)smp;
#pragma unroll
    for (int k = 0; k < 2; ++k) {
        int idx = tid + k * 256;           // 0..511
        int bbl = idx >> 6, cc = idx & 63;
        int b = b0 + bbl, c = c0 + cc;
        float bias = conv_b[l * DD + c];
        float h1 = 0.f, h2 = 0.f, h3 = 0.f, o = 0.f;
#pragma unroll
        for (int t = 0; t < TT; ++t) {
            float x = fmaf(acc_s[(t * 8 + bbl) * EST_F + cc], inv, bias);
            float xr = x > 0.f ? x : 0.f;
            float f = sigmoid_pos(xr);
            float e = g_emb[((size_t)b * TT + t) * DD + c];
            h1 = fmaf(f, e - h1, h1);
            h2 = fmaf(f, h1 - h2, h2);
            h3 = fmaf(f, h2 - h3, h3);
            o += h3;
        }
        g_opart[((size_t)l * BB + b) * DD + c] = o;
    }
}

// ---------------- 2) reduce over l -------------------------------------------
__global__ void reduce_o_kernel() {
    int idx = blockIdx.x * blockDim.x + threadIdx.x;
    float o = 0.f;
#pragma unroll
    for (int l = 0; l < LL; ++l) o += g_opart[(size_t)l * BB * DD + idx];
    g_o[idx] = o;
}

// ---------------- 3) z = [o, user_emb] @ fc1_w^T + fc1_b --------------------
__global__ void fc_kernel(const int* __restrict__ user_var,
                          const float* __restrict__ user_emb,
                          const float* __restrict__ fc1_w,
                          const float* __restrict__ fc1_b) {
    __shared__ float cat_s[8][2 * DD];
    int b0 = blockIdx.x * 8;
    int i0 = blockIdx.y * 8;
    int tid = threadIdx.x;
    for (int it = tid; it < 8 * (2 * DD / 4); it += 256) {
        int bb = it >> 7;
        int j4 = it & 127;
        float4 v;
        if (j4 < DD / 4)
            v = ((const float4*)(g_o + (size_t)(b0 + bb) * DD))[j4];
        else
            v = ((const float4*)(user_emb + (size_t)user_var[b0 + bb] * DD))[j4 - DD / 4];
        *(float4*)&cat_s[bb][j4 * 4] = v;
    }
    __syncthreads();
    int warp = tid >> 5, lane = tid & 31;
    int i = i0 + warp;
    float accv[8];
#pragma unroll
    for (int bb = 0; bb < 8; bb++) accv[bb] = 0.f;
    for (int j = lane; j < 2 * DD; j += 32) {
        float w = fc1_w[(size_t)i * (2 * DD) + j];
#pragma unroll
        for (int bb = 0; bb < 8; bb++) accv[bb] += w * cat_s[bb][j];
    }
#pragma unroll
    for (int bb = 0; bb < 8; bb++) {
        float v = accv[bb];
#pragma unroll
        for (int off = 16; off; off >>= 1) v += __shfl_down_sync(0xffffffffu, v, off);
        if (lane == 0) g_z[(size_t)(b0 + bb) * DD + i] = v + fc1_b[i];
    }
}

// ---------------- 4) res[b,n] = W2[item] . z[b] + b2 ------------------------
__global__ void out_kernel(const int* __restrict__ item_var,
                           const float* __restrict__ W2,
                           const float* __restrict__ b2,
                           float* __restrict__ out) {
    int gw = (blockIdx.x * blockDim.x + threadIdx.x) >> 5;
    int lane = threadIdx.x & 31;
    if (gw >= BB * NTGT) return;
    int b = gw >> 5;
    int iv = item_var[gw];
    const float* w = W2 + (size_t)iv * DD;
    const float* zz = g_z + (size_t)b * DD;
    float acc = 0.f;
    for (int d = lane; d < DD; d += 32) acc += w[d] * zz[d];
#pragma unroll
    for (int off = 16; off; off >>= 1) acc += __shfl_down_sync(0xffffffffu, acc, off);
    if (lane == 0) out[gw] = acc + b2[iv];
}

// ---------------- launch ------------------------------------------------------
extern "C" void kernel_launch(void* const* d_in, const int* in_sizes, int n_in,
                              void* d_out, int out_size) {
    const int*   seq_var  = (const int*)d_in[0];
    const int*   user_var = (const int*)d_in[1];
    const int*   item_var = (const int*)d_in[2];
    const float* item_emb = (const float*)d_in[3];
    const float* user_emb = (const float*)d_in[4];
    const float* conv_w   = (const float*)d_in[5];
    const float* conv_b   = (const float*)d_in[6];
    const float* fc1_w    = (const float*)d_in[7];
    const float* fc1_b    = (const float*)d_in[8];
    const float* W2       = (const float*)d_in[9];
    const float* b2       = (const float*)d_in[10];
    float* out = (float*)d_out;

    build_lut_kernel<<<1, 136>>>();
    gather_emb_kernel<<<NROW, 64>>>(seq_var, item_emb);
    {
        int* lut_ptr = nullptr;
        cudaGetSymbolAddress((void**)&lut_ptr, d_pair_lut);
        wconv_kernel<<<dim3(64, 136), 256>>>(conv_w, lut_ptr);
    }

    cudaFuncSetAttribute(conv_fused_kernel,
                         cudaFuncAttributeMaxDynamicSharedMemorySize, SMEM_REQ);
    conv_fused_kernel<<<dim3(4, BB / 8, LL), 256, SMEM_REQ>>>(conv_b);

    reduce_o_kernel<<<BB * DD / 256, 256>>>();
    fc_kernel<<<dim3(BB / 8, DD / 8), 256>>>(user_var, user_emb, fc1_w, fc1_b);
    out_kernel<<<(BB * NTGT * 32) / 256, 256>>>(item_var, W2, b2, out);
}

// round 11
// speedup vs baseline: 1.1852x; 1.0221x over previous
#include <cuda_runtime.h>
#include <cuda_bf16.h>
#include <math.h>
#include <stdint.h>

#define BB 512
#define TT 16
#define DD 256
#define LL 16
#define NTGT 32
#define NROW (BB*TT)

// ---------------- scratch (device globals) ----------------------------------
__device__ float         g_emb  [NROW*DD];             // fp32 emb    8 MB
__device__ unsigned char g_emb8 [NROW*DD];             // e4m3 emb*64 2 MB
__device__ unsigned char g_w8   [LL*LL*DD*DD];         // e4m3 w*64  16.7 MB
__device__ float         g_opart[LL*BB*DD];            // per-l o     8 MB
__device__ float         g_o    [BB*DD];
__device__ float         g_z    [BB*DD];

// ---------------- helpers ----------------------------------------------------
__device__ __forceinline__ uint32_t smem_u32(const void* p) {
    uint32_t a;
    asm("{ .reg .u64 t; cvta.to.shared.u64 t, %1; cvt.u32.u64 %0, t; }"
        : "=r"(a) : "l"(p));
    return a;
}
__device__ __forceinline__ void cpa16(uint32_t s, const void* g) {
    asm volatile("cp.async.cg.shared.global [%0], [%1], 16;"
                 :: "r"(s), "l"(g) : "memory");
}
#define CP_COMMIT() asm volatile("cp.async.commit_group;" ::: "memory")

__device__ __forceinline__ void ldsm4(uint32_t (&r)[4], uint32_t a) {
    asm volatile("ldmatrix.sync.aligned.m8n8.x4.shared.b16 {%0,%1,%2,%3}, [%4];"
                 : "=r"(r[0]), "=r"(r[1]), "=r"(r[2]), "=r"(r[3]) : "r"(a));
}
__device__ __forceinline__ void mma_fp8(float (&c)[4], const uint32_t (&a)[4],
                                        uint32_t b0, uint32_t b1) {
    asm volatile(
        "mma.sync.aligned.m16n8k32.row.col.f32.e4m3.e4m3.f32 "
        "{%0,%1,%2,%3}, {%4,%5,%6,%7}, {%8,%9}, {%0,%1,%2,%3};"
        : "+f"(c[0]), "+f"(c[1]), "+f"(c[2]), "+f"(c[3])
        : "r"(a[0]), "r"(a[1]), "r"(a[2]), "r"(a[3]), "r"(b0), "r"(b1));
}
__device__ __forceinline__ uint16_t cvt_e4m3x2(float hi, float lo) {
    uint16_t r;
    asm("cvt.rn.satfinite.e4m3x2.f32 %0, %1, %2;" : "=h"(r) : "f"(hi), "f"(lo));
    return r;
}
__device__ __forceinline__ float sigmoid_pos(float x) {
    if (x < 0.25f) {
        float x2 = x * x;
        float p = fmaf(x2, 1.0f / 480.0f, -1.0f / 48.0f);
        p = fmaf(x2, p, 0.25f);
        return fmaf(x, p, 0.5f);
    }
    return 1.0f / (1.0f + expf(-x));
}

// ---------------- 0a) gather item embeddings (fp32 + e4m3*64) ---------------
__global__ void gather_emb_kernel(const int* __restrict__ seq,
                                  const float* __restrict__ item_emb) {
    int row = blockIdx.x;
    int idx = seq[row];
    float4 v = ((const float4*)(item_emb + (size_t)idx * DD))[threadIdx.x];
    ((float4*)(g_emb + (size_t)row * DD))[threadIdx.x] = v;
    uint32_t p01 = cvt_e4m3x2(v.y * 64.f, v.x * 64.f);
    uint32_t p23 = cvt_e4m3x2(v.w * 64.f, v.z * 64.f);
    ((uint32_t*)g_emb8)[(size_t)row * 64 + threadIdx.x] = p01 | (p23 << 16);
}

// ---------------- 0b) conv_w fp32 -> e4m3*64 (valid pairs only) --------------
__device__ int d_pair_lut[136];
__global__ void build_lut_kernel() {
    int p = threadIdx.x;
    if (p < 136) {
        int l = 0, a = 0;
        while (a + l + 1 <= p) { a += l + 1; l++; }
        d_pair_lut[p] = l * 16 + (p - a);
    }
}
__global__ void wconv_kernel(const float* __restrict__ conv_w,
                             const int* __restrict__ pair_lut) {
    int p = blockIdx.y;
    int lm = pair_lut[p];
    size_t base = (size_t)lm * DD * DD;
    int i = blockIdx.x * 256 + threadIdx.x;
    float4 v = ((const float4*)(conv_w + base))[i];
    uint32_t p01 = cvt_e4m3x2(v.y * 64.f, v.x * 64.f);
    uint32_t p23 = cvt_e4m3x2(v.w * 64.f, v.z * 64.f);
    ((uint32_t*)(g_w8 + base))[i] = p01 | (p23 << 16);
}

// ---------------- 1) fused windowed fp8 GEMM + gate + QRNN -------------------
// CTA: 512 thr / 16 warps (warpM 0..3 x warpN 0..3).
// l fixed, 8 b x 16 t (M=128, tile = 8b x 2t pair) x 128 c.
// Warp: pairs {warpM, warpM+4}, 32 c. Chunk = one tap (256B K), ring-2 B.
#define AST_B   272
#define A_SZ    (128*AST_B)            // 34816
#define ZOFF    A_SZ
#define B_OFF0  (A_SZ + AST_B)         // 35088
#define B_SZ    (128*AST_B)            // 34816 (128 c-rows x 272B, 256B payload)
#define SMEM_REQ (B_OFF0 + 2*B_SZ)     // 104720
#define EST_F   132                    // epilogue fp32 row stride (floats)

__global__ void __launch_bounds__(512, 2)
conv_fused_kernel(const float* __restrict__ conv_b) {
    extern __shared__ char smp[];
    const uint32_t sb = smem_u32(smp);
    const int tid = threadIdx.x, wid = tid >> 5, lane = tid & 31;
    const int warpM = wid >> 2, warpN = wid & 3;

    const int l  = 15 - blockIdx.z;
    const int b0 = blockIdx.y * 8;
    const int c0 = blockIdx.x * 128;

    // ---- stage A panel: row (t'*8+bi) <- emb8[b0+bi][t'], 256B payload ----
    {
#pragma unroll
        for (int it = 0; it < 4; ++it) {
            int i = tid + it * 512;          // 0..2047
            int r = i >> 4, q = i & 15;
            int tp = r >> 3, bi2 = r & 7;
            const uint4* src = (const uint4*)g_emb8
                             + ((size_t)(b0 + bi2) * TT + tp) * 16 + q;
            *(uint4*)(smp + r * AST_B + q * 16) = *src;
        }
        if (tid < 17) *(uint4*)(smp + ZOFF + tid * 16) = make_uint4(0, 0, 0, 0);
    }

    // lane constants
    const int t_ln = (lane & 7) + ((lane >> 3) & 1) * 8;   // A tile row 0..15
    const int ti   = t_ln >> 3;                             // t within pair
    const int bi   = t_ln & 7;                              // b within group
    const int kh_a = lane >> 4;
    const int n_ln = ((lane >> 4) << 3) + (lane & 7);
    const int kh_b = (lane >> 3) & 1;

    const unsigned char* Wl = g_w8 + (size_t)l * LL * DD * DD + (size_t)c0 * DD;

    float acc[2][4][4];
#pragma unroll
    for (int i = 0; i < 2; i++)
#pragma unroll
        for (int j = 0; j < 4; j++)
#pragma unroll
            for (int k = 0; k < 4; k++) acc[i][j][k] = 0.f;

    const int nch = l + 1;

    // B chunk = tap m: 128 c-rows x 256B
    auto issueB = [&](int m) {
        const unsigned char* wb = Wl + (size_t)m * DD * DD;
        uint32_t sdst = sb + B_OFF0 + (m & 1) * B_SZ;
#pragma unroll
        for (int it = 0; it < 4; ++it) {
            int i = tid + it * 512;          // 2048 x 16B
            int ci = i >> 4, q = i & 15;
            cpa16(sdst + ci * AST_B + q * 16, wb + (size_t)ci * DD + q * 16);
        }
        CP_COMMIT();
    };

    issueB(0);
    if (nch > 1) issueB(1);

    // per-warp/lane B ldsm bases (offset within a buffer)
    const uint32_t boff0 = (uint32_t)((warpN * 32 + n_ln) * AST_B + kh_b * 16);
    const uint32_t boff1 = boff0 + 16 * AST_B;

    for (int m = 0; m < nch; ++m) {
        if (m + 1 < nch) asm volatile("cp.async.wait_group 1;" ::: "memory");
        else             asm volatile("cp.async.wait_group 0;" ::: "memory");
        __syncthreads();
        if (m + 2 < nch) issueB(m + 2);

        const bool v0 = (2 * warpM + 1) >= m;
        const bool v1 = true;                    // pair warpM+4: 2*(wM+4)+1 >= 9 >= m? m<=15
        // pair1 = warpM+4 -> 2*pair1+1 = 2*warpM+9; invalid only when m > 2*warpM+9
        const bool v1r = (2 * (warpM + 4) + 1) >= m;
        if (!v0 && !v1r) continue;

        const uint32_t bbase = sb + B_OFF0 + (m & 1) * B_SZ;
        const uint32_t b_ld0 = bbase + boff0;
        const uint32_t b_ld1 = bbase + boff1;

        uint32_t arow[2];
        bool val[2] = {v0, v1r};
        {
            int tp0 = 2 * warpM + ti - m;
            int tp1 = 2 * (warpM + 4) + ti - m;
            arow[0] = (tp0 >= 0)
                ? sb + (uint32_t)((tp0 * 8 + bi) * AST_B + kh_a * 16)
                : sb + (uint32_t)(ZOFF + kh_a * 16);
            arow[1] = (tp1 >= 0)
                ? sb + (uint32_t)((tp1 * 8 + bi) * AST_B + kh_a * 16)
                : sb + (uint32_t)(ZOFF + kh_a * 16);
        }

#pragma unroll
        for (int ks = 0; ks < 8; ++ks) {           // 8 x k32 = 256B
            uint32_t bfr[2][4];
            ldsm4(bfr[0], b_ld0 + ks * 32);
            ldsm4(bfr[1], b_ld1 + ks * 32);
#pragma unroll
            for (int mt = 0; mt < 2; ++mt) {
                if (!val[mt]) continue;
                uint32_t a[4];
                ldsm4(a, arow[mt] + ks * 32);
#pragma unroll
                for (int ns = 0; ns < 4; ++ns)
                    mma_fp8(acc[mt][ns], a,
                            bfr[ns >> 1][(ns & 1) * 2],
                            bfr[ns >> 1][(ns & 1) * 2 + 1]);
            }
        }
    }
    __syncthreads();

    // ---- epilogue: write all 128 rows (row = t*8 + b), 128 c, 528B stride ----
    {
        const int r0 = lane >> 2;          // b lane of acc rows
        const int c2 = (lane & 3) * 2;
#pragma unroll
        for (int mt = 0; mt < 2; ++mt) {
            int pair = warpM + 4 * mt;
#pragma unroll
            for (int ns = 0; ns < 4; ++ns) {
                int col = warpN * 32 + ns * 8 + c2;
                float2* p0 = (float2*)(smp + ((2 * pair)     * 8 + r0) * (EST_F * 4) + col * 4);
                float2* p1 = (float2*)(smp + ((2 * pair + 1) * 8 + r0) * (EST_F * 4) + col * 4);
                *p0 = make_float2(acc[mt][ns][0], acc[mt][ns][1]);
                *p1 = make_float2(acc[mt][ns][2], acc[mt][ns][3]);
            }
        }
    }
    __syncthreads();

    // ---- gate + 3x fo-pool + t-sum: 2 sequential (b,c) items per thread ----
    const float inv = 1.0f / 4096.0f;
    const float* acc_s = (const float*)smp;
#pragma unroll
    for (int k = 0; k < 2; ++k) {
        int idx = tid + k * 512;           // 0..1023
        int bbl = idx >> 7, cc = idx & 127;
        int b = b0 + bbl, c = c0 + cc;
        float bias = conv_b[l * DD + c];
        float h1 = 0.f, h2 = 0.f, h3 = 0.f, o = 0.f;
#pragma unroll
        for (int t = 0; t < TT; ++t) {
            float x = fmaf(acc_s[(t * 8 + bbl) * EST_F + cc], inv, bias);
            float xr = x > 0.f ? x : 0.f;
            float f = sigmoid_pos(xr);
            float e = g_emb[((size_t)b * TT + t) * DD + c];
            h1 = fmaf(f, e - h1, h1);
            h2 = fmaf(f, h1 - h2, h2);
            h3 = fmaf(f, h2 - h3, h3);
            o += h3;
        }
        g_opart[((size_t)l * BB + b) * DD + c] = o;
    }
}

// ---------------- 2) reduce over l -------------------------------------------
__global__ void reduce_o_kernel() {
    int idx = blockIdx.x * blockDim.x + threadIdx.x;
    float o = 0.f;
#pragma unroll
    for (int l = 0; l < LL; ++l) o += g_opart[(size_t)l * BB * DD + idx];
    g_o[idx] = o;
}

// ---------------- 3) z = [o, user_emb] @ fc1_w^T + fc1_b --------------------
__global__ void fc_kernel(const int* __restrict__ user_var,
                          const float* __restrict__ user_emb,
                          const float* __restrict__ fc1_w,
                          const float* __restrict__ fc1_b) {
    __shared__ float cat_s[8][2 * DD];
    int b0 = blockIdx.x * 8;
    int i0 = blockIdx.y * 8;
    int tid = threadIdx.x;
    for (int it = tid; it < 8 * (2 * DD / 4); it += 256) {
        int bb = it >> 7;
        int j4 = it & 127;
        float4 v;
        if (j4 < DD / 4)
            v = ((const float4*)(g_o + (size_t)(b0 + bb) * DD))[j4];
        else
            v = ((const float4*)(user_emb + (size_t)user_var[b0 + bb] * DD))[j4 - DD / 4];
        *(float4*)&cat_s[bb][j4 * 4] = v;
    }
    __syncthreads();
    int warp = tid >> 5, lane = tid & 31;
    int i = i0 + warp;
    float accv[8];
#pragma unroll
    for (int bb = 0; bb < 8; bb++) accv[bb] = 0.f;
    for (int j = lane; j < 2 * DD; j += 32) {
        float w = fc1_w[(size_t)i * (2 * DD) + j];
#pragma unroll
        for (int bb = 0; bb < 8; bb++) accv[bb] += w * cat_s[bb][j];
    }
#pragma unroll
    for (int bb = 0; bb < 8; bb++) {
        float v = accv[bb];
#pragma unroll
        for (int off = 16; off; off >>= 1) v += __shfl_down_sync(0xffffffffu, v, off);
        if (lane == 0) g_z[(size_t)(b0 + bb) * DD + i] = v + fc1_b[i];
    }
}

// ---------------- 4) res[b,n] = W2[item] . z[b] + b2 ------------------------
__global__ void out_kernel(const int* __restrict__ item_var,
                           const float* __restrict__ W2,
                           const float* __restrict__ b2,
                           float* __restrict__ out) {
    int gw = (blockIdx.x * blockDim.x + threadIdx.x) >> 5;
    int lane = threadIdx.x & 31;
    if (gw >= BB * NTGT) return;
    int b = gw >> 5;
    int iv = item_var[gw];
    const float* w = W2 + (size_t)iv * DD;
    const float* zz = g_z + (size_t)b * DD;
    float acc = 0.f;
    for (int d = lane; d < DD; d += 32) acc += w[d] * zz[d];
#pragma unroll
    for (int off = 16; off; off >>= 1) acc += __shfl_down_sync(0xffffffffu, acc, off);
    if (lane == 0) out[gw] = acc + b2[iv];
}

// ---------------- launch ------------------------------------------------------
extern "C" void kernel_launch(void* const* d_in, const int* in_sizes, int n_in,
                              void* d_out, int out_size) {
    const int*   seq_var  = (const int*)d_in[0];
    const int*   user_var = (const int*)d_in[1];
    const int*   item_var = (const int*)d_in[2];
    const float* item_emb = (const float*)d_in[3];
    const float* user_emb = (const float*)d_in[4];
    const float* conv_w   = (const float*)d_in[5];
    const float* conv_b   = (const float*)d_in[6];
    const float* fc1_w    = (const float*)d_in[7];
    const float* fc1_b    = (const float*)d_in[8];
    const float* W2       = (const float*)d_in[9];
    const float* b2       = (const float*)d_in[10];
    float* out = (float*)d_out;

    build_lut_kernel<<<1, 136>>>();
    gather_emb_kernel<<<NROW, 64>>>(seq_var, item_emb);
    {
        int* lut_ptr = nullptr;
        cudaGetSymbolAddress((void**)&lut_ptr, d_pair_lut);
        wconv_kernel<<<dim3(64, 136), 256>>>(conv_w, lut_ptr);
    }

    cudaFuncSetAttribute(conv_fused_kernel,
                         cudaFuncAttributeMaxDynamicSharedMemorySize, SMEM_REQ);
    conv_fused_kernel<<<dim3(2, BB / 8, LL), 512, SMEM_REQ>>>(conv_b);

    reduce_o_kernel<<<BB * DD / 256, 256>>>();
    fc_kernel<<<dim3(BB / 8, DD / 8), 256>>>(user_var, user_emb, fc1_w, fc1_b);
    out_kernel<<<(BB * NTGT * 32) / 256, 256>>>(item_var, W2, b2, out);
}